// round 1
// baseline (speedup 1.0000x reference)
#include <cuda_runtime.h>
#include <cuda_bf16.h>
#include <math.h>

// Problem constants
#define B_   256
#define G_   20000
#define L_   512
#define GD_  256
#define H_   8
#define HD_  64
#define SCALE_ 0.125f
#define SPLITS_ 25          // split-K for ctx GEMM: 20000/25 = 800 per split

// ------------------------- device scratch (static; no allocs) ---------------
__device__ float g_Q[B_ * L_];
__device__ float g_K[G_ * L_];
__device__ float g_V[G_ * L_];
__device__ float g_ctxp[H_ * SPLITS_ * B_ * HD_];
__device__ float g_ctx[B_ * L_];
__device__ float g_h[B_ * L_];

// ------------------------- tiled SGEMM: C = alpha * A @ B^T (+bias) ---------
// A: [M,K] row-major (lda), B: [N,K] row-major (ldb), C: [M,N] (ldc).
// Per-z (head) pointer offsets aZ/bZ/cZ. BM=128, BN=64, BK=16, 256 threads,
// 8x4 per-thread microtile.
#define BM 128
#define BN 64
#define BK 16
#define TM 8
#define TN 4

__global__ __launch_bounds__(256) void gemm_tn(
    const float* __restrict__ A, const float* __restrict__ B,
    float* __restrict__ C, const float* __restrict__ bias,
    int M, int N, int K, int lda, int ldb, long ldc,
    long aZ, long bZ, long cZ, float alpha)
{
    A += (long)blockIdx.z * aZ;
    B += (long)blockIdx.z * bZ;
    C += (long)blockIdx.z * cZ;

    const int m0 = blockIdx.y * BM;
    const int n0 = blockIdx.x * BN;

    __shared__ float As[BM][BK + 1];
    __shared__ float Bs[BN][BK + 1];

    const int tid = threadIdx.x;
    const int tx = tid & 15;          // 0..15 -> N
    const int ty = tid >> 4;          // 0..15 -> M

    float acc[TM][TN];
#pragma unroll
    for (int i = 0; i < TM; i++)
#pragma unroll
        for (int j = 0; j < TN; j++) acc[i][j] = 0.f;

    for (int k0 = 0; k0 < K; k0 += BK) {
        // load A tile: 128x16 = 2048 elems, 8/thread, k fastest (coalesced)
#pragma unroll
        for (int i = 0; i < 8; i++) {
            int e = tid + i * 256;
            int k = e & 15;
            int m = e >> 4;
            int gm = m0 + m, gk = k0 + k;
            float v = 0.f;
            if (gm < M && gk < K) v = A[(long)gm * lda + gk];
            As[m][k] = v;
        }
        // load B tile: 64x16 = 1024 elems, 4/thread
#pragma unroll
        for (int i = 0; i < 4; i++) {
            int e = tid + i * 256;
            int k = e & 15;
            int n = e >> 4;
            int gn = n0 + n, gk = k0 + k;
            float v = 0.f;
            if (gn < N && gk < K) v = B[(long)gn * ldb + gk];
            Bs[n][k] = v;
        }
        __syncthreads();
#pragma unroll
        for (int k = 0; k < BK; k++) {
            float ra[TM], rb[TN];
#pragma unroll
            for (int i = 0; i < TM; i++) ra[i] = As[ty * TM + i][k];
#pragma unroll
            for (int j = 0; j < TN; j++) rb[j] = Bs[tx * TN + j][k];
#pragma unroll
            for (int i = 0; i < TM; i++)
#pragma unroll
                for (int j = 0; j < TN; j++) acc[i][j] += ra[i] * rb[j];
        }
        __syncthreads();
    }

#pragma unroll
    for (int i = 0; i < TM; i++) {
        int gm = m0 + ty * TM + i;
        if (gm >= M) continue;
#pragma unroll
        for (int j = 0; j < TN; j++) {
            int gn = n0 + tx * TN + j;
            if (gn >= N) continue;
            float v = acc[i][j] * alpha;
            if (bias) v += bias[gn];
            C[(long)gm * ldc + gn] = v;
        }
    }
}

// ------------------------- ctx GEMM with split-K -----------------------------
// partial[z][b][d] = sum_{g in split} attn[(b*H+h)*G + g] * V[g*L + h*HD + d]
// z = h*SPLITS + s. Grid: (1, ceil(B/BM), H*SPLITS).
__global__ __launch_bounds__(256) void ctx_gemm(
    const float* __restrict__ attn, const float* __restrict__ V,
    float* __restrict__ part)
{
    const int z = blockIdx.z;
    const int h = z / SPLITS_;
    const int s = z % SPLITS_;
    const int chunk = G_ / SPLITS_;         // 800
    const int kb = s * chunk;

    const float* A = attn + (long)h * G_;   // row b: stride H_*G_
    const float* Bp = V + h * HD_;          // row g: stride L_
    float* C = part + (long)z * B_ * HD_;

    const int m0 = blockIdx.y * BM;

    __shared__ float As[BM][BK + 1];
    __shared__ float Bs[BK][BN];

    const int tid = threadIdx.x;
    const int tx = tid & 15;
    const int ty = tid >> 4;

    float acc[TM][TN];
#pragma unroll
    for (int i = 0; i < TM; i++)
#pragma unroll
        for (int j = 0; j < TN; j++) acc[i][j] = 0.f;

    for (int k0 = 0; k0 < chunk; k0 += BK) {
#pragma unroll
        for (int i = 0; i < 8; i++) {
            int e = tid + i * 256;
            int k = e & 15;
            int m = e >> 4;
            int gm = m0 + m;
            float v = 0.f;
            if (gm < B_) v = A[(long)gm * (H_ * G_) + kb + k0 + k];
            As[m][k] = v;
        }
#pragma unroll
        for (int i = 0; i < 4; i++) {
            int e = tid + i * 256;
            int n = e & 63;
            int k = e >> 6;
            Bs[k][n] = Bp[(long)(kb + k0 + k) * L_ + n];
        }
        __syncthreads();
#pragma unroll
        for (int k = 0; k < BK; k++) {
            float ra[TM], rb[TN];
#pragma unroll
            for (int i = 0; i < TM; i++) ra[i] = As[ty * TM + i][k];
#pragma unroll
            for (int j = 0; j < TN; j++) rb[j] = Bs[k][tx * TN + j];
#pragma unroll
            for (int i = 0; i < TM; i++)
#pragma unroll
                for (int j = 0; j < TN; j++) acc[i][j] += ra[i] * rb[j];
        }
        __syncthreads();
    }

#pragma unroll
    for (int i = 0; i < TM; i++) {
        int gm = m0 + ty * TM + i;
        if (gm >= B_) continue;
#pragma unroll
        for (int j = 0; j < TN; j++) {
            int gn = tx * TN + j;
            C[(long)gm * HD_ + gn] = acc[i][j];
        }
    }
}

// ------------------------- deterministic split-K reduce ----------------------
__global__ void reduce_ctx(const float* __restrict__ part, float* __restrict__ ctx)
{
    int idx = blockIdx.x * blockDim.x + threadIdx.x;   // 0 .. B_*L_-1
    if (idx >= B_ * L_) return;
    int b = idx / L_;
    int c = idx % L_;
    int h = c / HD_;
    int d = c % HD_;
    float s = 0.f;
    for (int i = 0; i < SPLITS_; i++)
        s += part[(((long)h * SPLITS_ + i) * B_ + b) * HD_ + d];
    ctx[idx] = s;
}

// ------------------------- row softmax over G (in place) ---------------------
__global__ void softmax_rows(float* __restrict__ a)
{
    float* p = a + (long)blockIdx.x * G_;
    __shared__ float red[256];
    const int t = threadIdx.x;

    float mx = -1e30f;
    for (int i = t; i < G_; i += 256) mx = fmaxf(mx, p[i]);
    red[t] = mx; __syncthreads();
    for (int s = 128; s > 0; s >>= 1) {
        if (t < s) red[t] = fmaxf(red[t], red[t + s]);
        __syncthreads();
    }
    mx = red[0]; __syncthreads();

    float sm = 0.f;
    for (int i = t; i < G_; i += 256) sm += __expf(p[i] - mx);
    red[t] = sm; __syncthreads();
    for (int s = 128; s > 0; s >>= 1) {
        if (t < s) red[t] += red[t + s];
        __syncthreads();
    }
    const float inv = 1.f / red[0];

    for (int i = t; i < G_; i += 256) p[i] = __expf(p[i] - mx) * inv;
}

// ------------------------- LayerNorm + ReLU (in place, row = 512) ------------
__global__ void ln_relu(float* __restrict__ hbuf,
                        const float* __restrict__ g, const float* __restrict__ bta)
{
    float* p = hbuf + (long)blockIdx.x * L_;
    __shared__ float r1[256];
    __shared__ float r2[256];
    const int t = threadIdx.x;
    float x0 = p[t], x1 = p[t + 256];
    r1[t] = x0 + x1;
    r2[t] = x0 * x0 + x1 * x1;
    __syncthreads();
    for (int s = 128; s > 0; s >>= 1) {
        if (t < s) { r1[t] += r1[t + s]; r2[t] += r2[t + s]; }
        __syncthreads();
    }
    float mu = r1[0] * (1.f / L_);
    float var = r2[0] * (1.f / L_) - mu * mu;
    float inv = rsqrtf(var + 1e-5f);
    float y0 = (x0 - mu) * inv * g[t] + bta[t];
    float y1 = (x1 - mu) * inv * g[t + 256] + bta[t + 256];
    p[t] = fmaxf(y0, 0.f);
    p[t + 256] = fmaxf(y1, 0.f);
}

// ------------------------- launch ---------------------------------------------
extern "C" void kernel_launch(void* const* d_in, const int* in_sizes, int n_in,
                              void* d_out, int out_size)
{
    const float* z_latent = (const float*)d_in[0];
    const float* gene_emb = (const float*)d_in[1];
    const float* Wq  = (const float*)d_in[2];
    const float* bq  = (const float*)d_in[3];
    const float* Wk  = (const float*)d_in[4];
    const float* bk  = (const float*)d_in[5];
    const float* Wv  = (const float*)d_in[6];
    const float* bv  = (const float*)d_in[7];
    const float* W1  = (const float*)d_in[8];
    const float* b1  = (const float*)d_in[9];
    const float* lng = (const float*)d_in[10];
    const float* lnb = (const float*)d_in[11];
    const float* W2  = (const float*)d_in[12];
    const float* b2  = (const float*)d_in[13];

    float* out_ga   = (float*)d_out;               // [B, G]
    float* out_attn = out_ga + (long)B_ * G_;      // [B, H, G] = [B*H rows][G]

    float *pQ, *pK, *pV, *pCtxp, *pCtx, *pH;
    cudaGetSymbolAddress((void**)&pQ,    g_Q);
    cudaGetSymbolAddress((void**)&pK,    g_K);
    cudaGetSymbolAddress((void**)&pV,    g_V);
    cudaGetSymbolAddress((void**)&pCtxp, g_ctxp);
    cudaGetSymbolAddress((void**)&pCtx,  g_ctx);
    cudaGetSymbolAddress((void**)&pH,    g_h);

    const int thr = 256;

    // 1. Q = z @ Wq^T + bq            [256,512]
    gemm_tn<<<dim3((L_ + BN - 1) / BN, (B_ + BM - 1) / BM, 1), thr>>>(
        z_latent, Wq, pQ, bq, B_, L_, L_, L_, L_, L_, 0, 0, 0, 1.f);

    // 2. K = ge @ Wk^T + bk           [20000,512]
    gemm_tn<<<dim3((L_ + BN - 1) / BN, (G_ + BM - 1) / BM, 1), thr>>>(
        gene_emb, Wk, pK, bk, G_, L_, GD_, GD_, GD_, L_, 0, 0, 0, 1.f);

    // 3. V = ge @ Wv^T + bv
    gemm_tn<<<dim3((L_ + BN - 1) / BN, (G_ + BM - 1) / BM, 1), thr>>>(
        gene_emb, Wv, pV, bv, G_, L_, GD_, GD_, GD_, L_, 0, 0, 0, 1.f);

    // 4. scores[b,h,g] = SCALE * Q[b,h,:]·K[g,h,:]   -> out_attn
    //    per-head offsets: A += h*64, B += h*64, C += h*20000 (ldc = H*G)
    gemm_tn<<<dim3((G_ + BN - 1) / BN, (B_ + BM - 1) / BM, H_), thr>>>(
        pQ, pK, out_attn, nullptr, B_, G_, HD_, L_, L_, (long)H_ * G_,
        HD_, HD_, G_, SCALE_);

    // 5. softmax over g, in place (rows (b,h) are contiguous length-G)
    softmax_rows<<<B_ * H_, 256>>>(out_attn);

    // 6. ctx split-K partials
    ctx_gemm<<<dim3(1, (B_ + BM - 1) / BM, H_ * SPLITS_), thr>>>(out_attn, pV, pCtxp);

    // 7. deterministic reduce -> ctx [256,512]
    reduce_ctx<<<(B_ * L_ + 255) / 256, 256>>>(pCtxp, pCtx);

    // 8. h = ctx @ W1^T + b1
    gemm_tn<<<dim3((L_ + BN - 1) / BN, (B_ + BM - 1) / BM, 1), thr>>>(
        pCtx, W1, pH, b1, B_, L_, L_, L_, L_, L_, 0, 0, 0, 1.f);

    // 9. LayerNorm + ReLU in place
    ln_relu<<<B_, 256>>>(pH, lng, lnb);

    // 10. gene_attention = h @ W2^T + b2   [256,20000]
    gemm_tn<<<dim3((G_ + BN - 1) / BN, (B_ + BM - 1) / BM, 1), thr>>>(
        pH, W2, out_ga, b2, B_, G_, L_, L_, L_, G_, 0, 0, 0, 1.f);
}

// round 3
// speedup vs baseline: 1.8257x; 1.8257x over previous
#include <cuda_runtime.h>
#include <cuda_bf16.h>
#include <cstdint>
#include <math.h>

// Problem constants
#define B_   256
#define G_   20000
#define L_   512
#define GD_  256
#define H_   8
#define HD_  64
#define SCALE_ 0.125f
#define CTX_SPLITS 16
#define CTX_CHUNK  1250     // 20000 / 16

// ------------------------- device scratch (static; no allocs) ---------------
__device__ float g_Q[B_ * L_];
__device__ float g_K[G_ * L_];
__device__ float g_V[G_ * L_];
__device__ float g_ctxp[H_ * CTX_SPLITS * B_ * HD_];
__device__ float g_ctx[B_ * L_];
__device__ float g_h[B_ * L_];

// ------------------------- bf16x3 mma.sync GEMM ------------------------------
// C[m,n] = alpha * sum_k A[m,k] * Bop[n,k] (+ bias[n])
// A: [M,K] fp32 row-major (lda). Bop: bKN==0 -> B[N,K] (ldb); bKN==1 -> B[K,N].
// batch: z = blockIdx.z; h = z/kSplit; s = z%kSplit.
//   A += h*aZ; B += h*bZ; C += z*cZ; k range = [s*kChunk, min(K,(s+1)*kChunk)).
// Split precision: x = hi + lo (bf16 each). Smem K-extent holds the concat
// [A_hi | A_lo | A_hi] x [B_hi | B_hi | B_lo], so one bf16 GEMM over 3*BK
// computes hi*hi + lo*hi + hi*lo (lo*lo dropped, ~2^-18).
//
// Tile: BM=128 x BN=64, BK=32 fp32 k per iter -> 96 bf16 k. 256 thr (8 warps),
// warp tile 32x32 via m16n8k16.

#define RS 104            // smem row stride in bf16 (96 + 8 pad)

__device__ __forceinline__ void mma16816(float* c, const uint32_t* a, const uint32_t* b)
{
    asm volatile(
        "mma.sync.aligned.m16n8k16.row.col.f32.bf16.bf16.f32 "
        "{%0,%1,%2,%3}, {%4,%5,%6,%7}, {%8,%9}, {%0,%1,%2,%3};"
        : "+f"(c[0]), "+f"(c[1]), "+f"(c[2]), "+f"(c[3])
        : "r"(a[0]), "r"(a[1]), "r"(a[2]), "r"(a[3]), "r"(b[0]), "r"(b[1]));
}

__device__ __forceinline__ uint32_t pack_hi(float x, float y,
                                            float* rx, float* ry)
{
    __nv_bfloat16 hx = __float2bfloat16(x);
    __nv_bfloat16 hy = __float2bfloat16(y);
    *rx = x - __bfloat162float(hx);
    *ry = y - __bfloat162float(hy);
    __nv_bfloat162 p = {hx, hy};
    return *(uint32_t*)&p;
}
__device__ __forceinline__ uint32_t pack_bf2(float x, float y)
{
    __nv_bfloat162 p = {__float2bfloat16(x), __float2bfloat16(y)};
    return *(uint32_t*)&p;
}

__global__ __launch_bounds__(256) void mma_gemm(
    const float* __restrict__ A, const float* __restrict__ B,
    float* __restrict__ C, const float* __restrict__ bias,
    int M, int N, int K, int lda, int ldb, long ldc,
    long aZ, long bZ, long cZ, int kSplit, int kChunk,
    float alpha, int bKN)
{
    __shared__ __align__(16) __nv_bfloat16 As[128 * RS];   // 26624 B
    __shared__ __align__(16) __nv_bfloat16 Bs[64 * RS];    // 13312 B

    const int tid = threadIdx.x;
    const int wid = tid >> 5, lane = tid & 31;
    const int grp = lane >> 2, tig = lane & 3;
    const int wm = wid & 3, wn = wid >> 2;

    const int z = blockIdx.z;
    const int h = z / kSplit, sK = z % kSplit;
    A += (long)h * aZ;
    B += (long)h * bZ;
    C += (long)z * cZ;
    const int kStart = sK * kChunk;
    const int kEnd = min(K, kStart + kChunk);
    const int m0 = blockIdx.y * 128, n0 = blockIdx.x * 64;

    float acc[2][4][4];
#pragma unroll
    for (int i = 0; i < 2; i++)
#pragma unroll
        for (int j = 0; j < 4; j++)
#pragma unroll
            for (int r = 0; r < 4; r++) acc[i][j][r] = 0.f;

    for (int k0 = kStart; k0 < kEnd; k0 += 32) {
        __syncthreads();
        // ---- A tile: 128 rows x 16 fp32-pairs
#pragma unroll
        for (int i = 0; i < 8; i++) {
            int e = tid + (i << 8);
            int kk = e & 15, m = e >> 4;
            int gm = m0 + m, gk = k0 + (kk << 1);
            float2 v = make_float2(0.f, 0.f);
            if (gm < M && gk < kEnd) v = *(const float2*)&A[(long)gm * lda + gk];
            float lx, ly;
            uint32_t hi = pack_hi(v.x, v.y, &lx, &ly);
            uint32_t lo = pack_bf2(lx, ly);
            uint32_t base = m * RS + (kk << 1);
            *(uint32_t*)(As + base)      = hi;
            *(uint32_t*)(As + base + 32) = lo;
            *(uint32_t*)(As + base + 64) = hi;
        }
        // ---- B tile: 64 n-rows x 32 k
        if (bKN == 0) {
#pragma unroll
            for (int i = 0; i < 4; i++) {
                int e = tid + (i << 8);
                int kk = e & 15, n = e >> 4;
                int gn = n0 + n, gk = k0 + (kk << 1);
                float2 v = make_float2(0.f, 0.f);
                if (gn < N && gk < kEnd) v = *(const float2*)&B[(long)gn * ldb + gk];
                float lx, ly;
                uint32_t hi = pack_hi(v.x, v.y, &lx, &ly);
                uint32_t lo = pack_bf2(lx, ly);
                uint32_t base = n * RS + (kk << 1);
                *(uint32_t*)(Bs + base)      = hi;
                *(uint32_t*)(Bs + base + 32) = hi;
                *(uint32_t*)(Bs + base + 64) = lo;
            }
        } else {
#pragma unroll
            for (int i = 0; i < 8; i++) {
                int e = tid + (i << 8);
                int n = e & 63, k = e >> 6;
                int gn = n0 + n, gk = k0 + k;
                float x = (gn < N && gk < kEnd) ? B[(long)gk * ldb + gn] : 0.f;
                __nv_bfloat16 hi = __float2bfloat16(x);
                __nv_bfloat16 lo = __float2bfloat16(x - __bfloat162float(hi));
                uint32_t base = n * RS + k;
                Bs[base]      = hi;
                Bs[base + 32] = hi;
                Bs[base + 64] = lo;
            }
        }
        __syncthreads();

        // ---- 6 k16 steps over the 96-wide concat
#pragma unroll
        for (int s = 0; s < 6; s++) {
            const int kb = s << 4;
            uint32_t af[2][4], bf[4][2];
#pragma unroll
            for (int mt = 0; mt < 2; mt++) {
                int r0 = (wm << 5) + (mt << 4) + grp;
                af[mt][0] = *(uint32_t*)(As + r0 * RS + kb + (tig << 1));
                af[mt][1] = *(uint32_t*)(As + (r0 + 8) * RS + kb + (tig << 1));
                af[mt][2] = *(uint32_t*)(As + r0 * RS + kb + (tig << 1) + 8);
                af[mt][3] = *(uint32_t*)(As + (r0 + 8) * RS + kb + (tig << 1) + 8);
            }
#pragma unroll
            for (int nt = 0; nt < 4; nt++) {
                int c0 = (wn << 5) + (nt << 3) + grp;
                bf[nt][0] = *(uint32_t*)(Bs + c0 * RS + kb + (tig << 1));
                bf[nt][1] = *(uint32_t*)(Bs + c0 * RS + kb + (tig << 1) + 8);
            }
#pragma unroll
            for (int mt = 0; mt < 2; mt++)
#pragma unroll
                for (int nt = 0; nt < 4; nt++)
                    mma16816(acc[mt][nt], af[mt], bf[nt]);
        }
    }

    // ---- epilogue
#pragma unroll
    for (int mt = 0; mt < 2; mt++) {
#pragma unroll
        for (int nt = 0; nt < 4; nt++) {
            int rm = m0 + (wm << 5) + (mt << 4) + grp;
            int cn = n0 + (wn << 5) + (nt << 3) + (tig << 1);
            if (cn < N) {
                float bx = 0.f, by = 0.f;
                if (bias) { bx = bias[cn]; by = bias[cn + 1]; }
                if (rm < M) {
                    float2 v;
                    v.x = acc[mt][nt][0] * alpha + bx;
                    v.y = acc[mt][nt][1] * alpha + by;
                    *(float2*)&C[(long)rm * ldc + cn] = v;
                }
                if (rm + 8 < M) {
                    float2 v;
                    v.x = acc[mt][nt][2] * alpha + bx;
                    v.y = acc[mt][nt][3] * alpha + by;
                    *(float2*)&C[(long)(rm + 8) * ldc + cn] = v;
                }
            }
        }
    }
}

// ------------------------- online 2-pass softmax over G ----------------------
__global__ void softmax2(float* __restrict__ a)
{
    float4* p = (float4*)(a + (long)blockIdx.x * G_);
    const int NV = G_ / 4;                  // 5000
    const int t = threadIdx.x;
    __shared__ float sm[256], ss[256];

    float m = -1e30f, s = 0.f;
    for (int i = t; i < NV; i += 256) {
        float4 v = p[i];
        float xs[4] = {v.x, v.y, v.z, v.w};
#pragma unroll
        for (int j = 0; j < 4; j++) {
            float x = xs[j];
            if (x <= m) {
                s += __expf(x - m);
            } else {
                s = s * __expf(m - x) + 1.f;
                m = x;
            }
        }
    }
    sm[t] = m; ss[t] = s;
    __syncthreads();
    for (int st = 128; st > 0; st >>= 1) {
        if (t < st) {
            float m2 = sm[t + st], s2 = ss[t + st];
            float M = fmaxf(sm[t], m2);
            ss[t] = ss[t] * __expf(sm[t] - M) + s2 * __expf(m2 - M);
            sm[t] = M;
        }
        __syncthreads();
    }
    const float mx = sm[0];
    const float inv = 1.f / ss[0];

    for (int i = t; i < NV; i += 256) {
        float4 v = p[i];
        v.x = __expf(v.x - mx) * inv;
        v.y = __expf(v.y - mx) * inv;
        v.z = __expf(v.z - mx) * inv;
        v.w = __expf(v.w - mx) * inv;
        p[i] = v;
    }
}

// ------------------------- deterministic split-K reduce ----------------------
__global__ void reduce_ctx(const float* __restrict__ part, float* __restrict__ ctx)
{
    int idx = blockIdx.x * blockDim.x + threadIdx.x;
    if (idx >= B_ * L_) return;
    int b = idx / L_;
    int c = idx % L_;
    int h = c / HD_;
    int d = c % HD_;
    float s = 0.f;
    for (int i = 0; i < CTX_SPLITS; i++)
        s += part[(((long)h * CTX_SPLITS + i) * B_ + b) * HD_ + d];
    ctx[idx] = s;
}

// ------------------------- LayerNorm + ReLU (in place, row = 512) ------------
__global__ void ln_relu(float* __restrict__ hbuf,
                        const float* __restrict__ g, const float* __restrict__ bta)
{
    float* p = hbuf + (long)blockIdx.x * L_;
    __shared__ float r1[256];
    __shared__ float r2[256];
    const int t = threadIdx.x;
    float x0 = p[t], x1 = p[t + 256];
    r1[t] = x0 + x1;
    r2[t] = x0 * x0 + x1 * x1;
    __syncthreads();
    for (int s = 128; s > 0; s >>= 1) {
        if (t < s) { r1[t] += r1[t + s]; r2[t] += r2[t + s]; }
        __syncthreads();
    }
    float mu = r1[0] * (1.f / L_);
    float var = r2[0] * (1.f / L_) - mu * mu;
    float inv = rsqrtf(var + 1e-5f);
    float y0 = (x0 - mu) * inv * g[t] + bta[t];
    float y1 = (x1 - mu) * inv * g[t + 256] + bta[t + 256];
    p[t] = fmaxf(y0, 0.f);
    p[t + 256] = fmaxf(y1, 0.f);
}

// ------------------------- launch ---------------------------------------------
extern "C" void kernel_launch(void* const* d_in, const int* in_sizes, int n_in,
                              void* d_out, int out_size)
{
    const float* z_latent = (const float*)d_in[0];
    const float* gene_emb = (const float*)d_in[1];
    const float* Wq  = (const float*)d_in[2];
    const float* bq  = (const float*)d_in[3];
    const float* Wk  = (const float*)d_in[4];
    const float* bk  = (const float*)d_in[5];
    const float* Wv  = (const float*)d_in[6];
    const float* bv  = (const float*)d_in[7];
    const float* W1  = (const float*)d_in[8];
    const float* b1  = (const float*)d_in[9];
    const float* lng = (const float*)d_in[10];
    const float* lnb = (const float*)d_in[11];
    const float* W2  = (const float*)d_in[12];
    const float* b2  = (const float*)d_in[13];

    float* out_ga   = (float*)d_out;               // [B, G]
    float* out_attn = out_ga + (long)B_ * G_;      // [B, H, G]

    float *pQ, *pK, *pV, *pCtxp, *pCtx, *pH;
    cudaGetSymbolAddress((void**)&pQ,    g_Q);
    cudaGetSymbolAddress((void**)&pK,    g_K);
    cudaGetSymbolAddress((void**)&pV,    g_V);
    cudaGetSymbolAddress((void**)&pCtxp, g_ctxp);
    cudaGetSymbolAddress((void**)&pCtx,  g_ctx);
    cudaGetSymbolAddress((void**)&pH,    g_h);

    // 1. Q = z @ Wq^T + bq                       [256,512]
    mma_gemm<<<dim3(8, 2, 1), 256>>>(
        z_latent, Wq, pQ, bq, B_, L_, L_, L_, L_, L_,
        0, 0, 0, 1, L_, 1.f, 0);

    // 2. K = ge @ Wk^T + bk                      [20000,512]
    mma_gemm<<<dim3(8, 157, 1), 256>>>(
        gene_emb, Wk, pK, bk, G_, L_, GD_, GD_, GD_, L_,
        0, 0, 0, 1, GD_, 1.f, 0);

    // 3. V = ge @ Wv^T + bv
    mma_gemm<<<dim3(8, 157, 1), 256>>>(
        gene_emb, Wv, pV, bv, G_, L_, GD_, GD_, GD_, L_,
        0, 0, 0, 1, GD_, 1.f, 0);

    // 4. scores[b,h,g] = SCALE * Q[b,h,:]·K[g,h,:]  -> out_attn (raw)
    mma_gemm<<<dim3(313, 2, H_), 256>>>(
        pQ, pK, out_attn, nullptr, B_, G_, HD_, L_, L_, (long)H_ * G_,
        HD_, HD_, G_, 1, HD_, SCALE_, 0);

    // 5. softmax over g, in place
    softmax2<<<B_ * H_, 256>>>(out_attn);

    // 6. ctx split-K partials: part[h,s][b][d] = attn_chunk @ V_head
    mma_gemm<<<dim3(1, 2, H_ * CTX_SPLITS), 256>>>(
        out_attn, pV, pCtxp, nullptr, B_, HD_, G_, (long)H_ * G_, L_, HD_,
        G_, HD_, (long)B_ * HD_, CTX_SPLITS, CTX_CHUNK, 1.f, 1);

    // 7. deterministic reduce -> ctx [256,512]
    reduce_ctx<<<(B_ * L_ + 255) / 256, 256>>>(pCtxp, pCtx);

    // 8. h = ctx @ W1^T + b1
    mma_gemm<<<dim3(8, 2, 1), 256>>>(
        pCtx, W1, pH, b1, B_, L_, L_, L_, L_, L_,
        0, 0, 0, 1, L_, 1.f, 0);

    // 9. LayerNorm + ReLU in place
    ln_relu<<<B_, 256>>>(pH, lng, lnb);

    // 10. gene_attention = h @ W2^T + b2         [256,20000]
    mma_gemm<<<dim3(313, 2, 1), 256>>>(
        pH, W2, out_ga, b2, B_, G_, L_, L_, L_, G_,
        0, 0, 0, 1, L_, 1.f, 0);
}